// round 5
// baseline (speedup 1.0000x reference)
#include <cuda_runtime.h>

// B=8 batches, N=1,000,000 vertices of 6 floats (pos[3], nrm[3]).
// out pos = T[:3,:4] @ [pos,1]   (bottom row is exactly [0,0,0,1] -> divide by 1 elided)
// out nrm = normalize(T[:3,:3] @ nrm), norm clamped at 1e-8.
// batch_indices input is unused by the reference.
//
// Streaming kernel: 4 vertices (96 B) per thread = 6 float4 loads + 6 float4 stores.
// Batch derived from blockIdx.x (block-uniform); transform staged via shared memory.

static constexpr int B_ = 8;
static constexpr int N_ = 1000000;
static constexpr int VERTS_PER_THREAD = 4;
static constexpr int QUADS_PER_BATCH = N_ / VERTS_PER_THREAD;   // 250,000
static constexpr int THREADS = 256;
static constexpr int BLOCKS_PER_BATCH = (QUADS_PER_BATCH + THREADS - 1) / THREADS;  // 977
static constexpr int TOTAL_BLOCKS = BLOCKS_PER_BATCH * B_;       // 7816

__device__ __forceinline__ void xform_one(
    float px, float py, float pz, float nx, float ny, float nz,
    float t00, float t01, float t02, float t03,
    float t10, float t11, float t12, float t13,
    float t20, float t21, float t22, float t23,
    float& ox, float& oy, float& oz, float& mx, float& my, float& mz)
{
    ox = fmaf(t00, px, fmaf(t01, py, fmaf(t02, pz, t03)));
    oy = fmaf(t10, px, fmaf(t11, py, fmaf(t12, pz, t13)));
    oz = fmaf(t20, px, fmaf(t21, py, fmaf(t22, pz, t23)));

    float ux = fmaf(t00, nx, fmaf(t01, ny, t02 * nz));
    float uy = fmaf(t10, nx, fmaf(t11, ny, t12 * nz));
    float uz = fmaf(t20, nx, fmaf(t21, ny, t22 * nz));
    float s  = fmaf(ux, ux, fmaf(uy, uy, uz * uz));
    float l  = fmaxf(sqrtf(s), 1e-8f);
    float inv = 1.0f / l;
    mx = ux * inv;
    my = uy * inv;
    mz = uz * inv;
}

__global__ void __launch_bounds__(THREADS)
vertex_xform_kernel(const float* __restrict__ verts,
                    const float* __restrict__ transforms,
                    float* __restrict__ out)
{
    __shared__ float sT[12];

    const int b      = blockIdx.x / BLOCKS_PER_BATCH;   // block-uniform
    const int blk_in = blockIdx.x - b * BLOCKS_PER_BATCH;

    if (threadIdx.x < 12)
        sT[threadIdx.x] = transforms[b * 16 + threadIdx.x];
    __syncthreads();

    const int q = blk_in * THREADS + threadIdx.x;
    if (q >= QUADS_PER_BATCH) return;

    // Broadcast LDS (conflict-free); held in registers for the thread lifetime.
    const float t00 = sT[0],  t01 = sT[1],  t02 = sT[2],  t03 = sT[3];
    const float t10 = sT[4],  t11 = sT[5],  t12 = sT[6],  t13 = sT[7];
    const float t20 = sT[8],  t21 = sT[9],  t22 = sT[10], t23 = sT[11];

    // 4 vertices = 96 bytes = 6 float4 (16B aligned: 96*q % 16 == 0)
    const size_t base = (size_t)b * ((size_t)N_ * 6 / 4) + (size_t)q * 6;  // float4 units
    const float4* __restrict__ vin = reinterpret_cast<const float4*>(verts) + base;

    // Batch all 6 loads up front for MLP.
    float4 a0 = vin[0];
    float4 a1 = vin[1];
    float4 a2 = vin[2];
    float4 a3 = vin[3];
    float4 a4 = vin[4];
    float4 a5 = vin[5];

    // v0: pos a0.xyz           nrm (a0.w, a1.x, a1.y)
    // v1: pos (a1.z,a1.w,a2.x) nrm a2.yzw
    // v2: pos a3.xyz           nrm (a3.w, a4.x, a4.y)
    // v3: pos (a4.z,a4.w,a5.x) nrm a5.yzw
    float o0x,o0y,o0z,m0x,m0y,m0z;
    float o1x,o1y,o1z,m1x,m1y,m1z;
    float o2x,o2y,o2z,m2x,m2y,m2z;
    float o3x,o3y,o3z,m3x,m3y,m3z;

    xform_one(a0.x,a0.y,a0.z, a0.w,a1.x,a1.y,
              t00,t01,t02,t03,t10,t11,t12,t13,t20,t21,t22,t23,
              o0x,o0y,o0z,m0x,m0y,m0z);
    xform_one(a1.z,a1.w,a2.x, a2.y,a2.z,a2.w,
              t00,t01,t02,t03,t10,t11,t12,t13,t20,t21,t22,t23,
              o1x,o1y,o1z,m1x,m1y,m1z);
    xform_one(a3.x,a3.y,a3.z, a3.w,a4.x,a4.y,
              t00,t01,t02,t03,t10,t11,t12,t13,t20,t21,t22,t23,
              o2x,o2y,o2z,m2x,m2y,m2z);
    xform_one(a4.z,a4.w,a5.x, a5.y,a5.z,a5.w,
              t00,t01,t02,t03,t10,t11,t12,t13,t20,t21,t22,t23,
              o3x,o3y,o3z,m3x,m3y,m3z);

    float4* __restrict__ vout = reinterpret_cast<float4*>(out) + base;
    vout[0] = make_float4(o0x, o0y, o0z, m0x);
    vout[1] = make_float4(m0y, m0z, o1x, o1y);
    vout[2] = make_float4(o1z, m1x, m1y, m1z);
    vout[3] = make_float4(o2x, o2y, o2z, m2x);
    vout[4] = make_float4(m2y, m2z, o3x, o3y);
    vout[5] = make_float4(o3z, m3x, m3y, m3z);
}

extern "C" void kernel_launch(void* const* d_in, const int* in_sizes, int n_in,
                              void* d_out, int out_size)
{
    const float* verts      = (const float*)d_in[0];  // (B, N, 6) float32
    // d_in[1] = batch_indices (unused)
    const float* transforms = (const float*)d_in[2];  // (B, 4, 4) float32
    float* out = (float*)d_out;                       // (B, N, 6) float32

    vertex_xform_kernel<<<TOTAL_BLOCKS, THREADS>>>(verts, transforms, out);
}

// round 6
// speedup vs baseline: 1.2313x; 1.2313x over previous
#include <cuda_runtime.h>

// B=8 batches, N=1,000,000 vertices of 6 floats (pos[3], nrm[3]).
// out pos = T[:3,:4] @ [pos,1]   (bottom row is exactly [0,0,0,1] -> divide elided)
// out nrm = normalize(T[:3,:3] @ nrm), norm clamped at 1e-8.
// batch_indices input is unused by the reference.
//
// R1 memory shape (best measured): 2 verts/thread = 48 B = 3 float4 loads+stores.
// Fixes vs R1: block-uniform batch + smem transform (kills 12 per-thread LDGs),
// streaming cache hints (__ldcs/__stcs) for the zero-reuse 768 MB working set.

static constexpr int B_ = 8;
static constexpr int N_ = 1000000;
static constexpr int PAIRS_PER_BATCH = N_ / 2;                 // 500,000
static constexpr int THREADS = 256;
static constexpr int BLOCKS_PER_BATCH = (PAIRS_PER_BATCH + THREADS - 1) / THREADS;  // 1954
static constexpr int TOTAL_BLOCKS = BLOCKS_PER_BATCH * B_;      // 15632

__device__ __forceinline__ void xform_one(
    float px, float py, float pz, float nx, float ny, float nz,
    float t00, float t01, float t02, float t03,
    float t10, float t11, float t12, float t13,
    float t20, float t21, float t22, float t23,
    float& ox, float& oy, float& oz, float& mx, float& my, float& mz)
{
    ox = fmaf(t00, px, fmaf(t01, py, fmaf(t02, pz, t03)));
    oy = fmaf(t10, px, fmaf(t11, py, fmaf(t12, pz, t13)));
    oz = fmaf(t20, px, fmaf(t21, py, fmaf(t22, pz, t23)));

    float ux = fmaf(t00, nx, fmaf(t01, ny, t02 * nz));
    float uy = fmaf(t10, nx, fmaf(t11, ny, t12 * nz));
    float uz = fmaf(t20, nx, fmaf(t21, ny, t22 * nz));
    float s  = fmaf(ux, ux, fmaf(uy, uy, uz * uz));
    float l  = fmaxf(sqrtf(s), 1e-8f);
    float inv = 1.0f / l;
    mx = ux * inv;
    my = uy * inv;
    mz = uz * inv;
}

__global__ void __launch_bounds__(THREADS)
vertex_xform_kernel(const float* __restrict__ verts,
                    const float* __restrict__ transforms,
                    float* __restrict__ out)
{
    __shared__ float sT[12];

    const int b      = blockIdx.x / BLOCKS_PER_BATCH;   // block-uniform
    const int blk_in = blockIdx.x - b * BLOCKS_PER_BATCH;

    if (threadIdx.x < 12)
        sT[threadIdx.x] = transforms[b * 16 + threadIdx.x];
    __syncthreads();

    const int p = blk_in * THREADS + threadIdx.x;       // pair index within batch
    if (p >= PAIRS_PER_BATCH) return;

    const float t00 = sT[0],  t01 = sT[1],  t02 = sT[2],  t03 = sT[3];
    const float t10 = sT[4],  t11 = sT[5],  t12 = sT[6],  t13 = sT[7];
    const float t20 = sT[8],  t21 = sT[9],  t22 = sT[10], t23 = sT[11];

    // 2 vertices = 48 bytes = 3 x float4 (16B aligned: 48*p % 16 == 0)
    const size_t base = (size_t)b * ((size_t)N_ * 6 / 4) + (size_t)p * 3;   // float4 units
    const float4* __restrict__ vin = reinterpret_cast<const float4*>(verts) + base;

    // Streaming loads (evict-first; zero reuse).
    float4 a0 = __ldcs(vin + 0);
    float4 a1 = __ldcs(vin + 1);
    float4 a2 = __ldcs(vin + 2);

    // v0: pos a0.xyz           nrm (a0.w, a1.x, a1.y)
    // v1: pos (a1.z,a1.w,a2.x) nrm a2.yzw
    float o0x,o0y,o0z,m0x,m0y,m0z;
    float o1x,o1y,o1z,m1x,m1y,m1z;

    xform_one(a0.x,a0.y,a0.z, a0.w,a1.x,a1.y,
              t00,t01,t02,t03,t10,t11,t12,t13,t20,t21,t22,t23,
              o0x,o0y,o0z,m0x,m0y,m0z);
    xform_one(a1.z,a1.w,a2.x, a2.y,a2.z,a2.w,
              t00,t01,t02,t03,t10,t11,t12,t13,t20,t21,t22,t23,
              o1x,o1y,o1z,m1x,m1y,m1z);

    float4* __restrict__ vout = reinterpret_cast<float4*>(out) + base;
    __stcs(vout + 0, make_float4(o0x, o0y, o0z, m0x));
    __stcs(vout + 1, make_float4(m0y, m0z, o1x, o1y));
    __stcs(vout + 2, make_float4(o1z, m1x, m1y, m1z));
}

extern "C" void kernel_launch(void* const* d_in, const int* in_sizes, int n_in,
                              void* d_out, int out_size)
{
    const float* verts      = (const float*)d_in[0];  // (B, N, 6) float32
    // d_in[1] = batch_indices (unused)
    const float* transforms = (const float*)d_in[2];  // (B, 4, 4) float32
    float* out = (float*)d_out;                       // (B, N, 6) float32

    vertex_xform_kernel<<<TOTAL_BLOCKS, THREADS>>>(verts, transforms, out);
}